// round 1
// baseline (speedup 1.0000x reference)
#include <cuda_runtime.h>
#include <math.h>

// Problem constants
#define BB 4
#define CC 128
#define HH 240
#define WW 320
#define NN 1024
#define NPTS (BB * NN)

__device__ float g_e1[NPTS];
__device__ float g_ld[NPTS];

__device__ __forceinline__ float warp_sum(float v) {
#pragma unroll
    for (int o = 16; o; o >>= 1) v += __shfl_xor_sync(0xffffffffu, v, o);
    return v;
}

__global__ __launch_bounds__(128) void gnloss_point_kernel(
    const float* __restrict__ Fa, const float* __restrict__ Fb,
    const float* __restrict__ ma, const float* __restrict__ mb,
    const float* __restrict__ noise)
{
    const int p = blockIdx.x;          // point index, 0..4095
    const int b = p >> 10;             // p / NN
    const int c = threadIdx.x;         // channel

    const float invL = 1.0f / 8.0f;    // 1/LEVEL
    const float xa  = ma[p * 2 + 0] * invL;
    const float ya  = ma[p * 2 + 1] * invL;
    const float ubx = mb[p * 2 + 0] * invL;
    const float uby = mb[p * 2 + 1] * invL;
    const float nx  = noise[p * 2 + 0];
    const float ny  = noise[p * 2 + 1];
    const float xs  = 2.0f * nx - 1.0f + ubx;
    const float ys  = 2.0f * ny - 1.0f + uby;

    // ---- f_t: bilinear sample of F_a at (xa, ya) ----
    const float* pa = Fa + (size_t)(b * CC + c) * (HH * WW);
    float fx0 = floorf(xa), fy0 = floorf(ya);
    float wxa = xa - fx0,  wya = ya - fy0;
    int ax0 = min(max((int)fx0, 0), WW - 1);
    int ax1 = min(ax0 + 1, WW - 1);
    int ay0 = min(max((int)fy0, 0), HH - 1);
    int ay1 = min(ay0 + 1, HH - 1);
    float a00 = pa[ay0 * WW + ax0], a01 = pa[ay0 * WW + ax1];
    float a10 = pa[ay1 * WW + ax0], a11 = pa[ay1 * WW + ax1];
    float ft = a00 * (1.0f - wxa) * (1.0f - wya) + a01 * wxa * (1.0f - wya)
             + a10 * (1.0f - wxa) * wya          + a11 * wxa * wya;

    // ---- F_b neighborhood for f_s, Jx, Jy ----
    const float* pb = Fb + (size_t)(b * CC + c) * (HH * WW);
    float gx0f = floorf(xs), gy0f = floorf(ys);
    float wx = xs - gx0f, wy = ys - gy0f;
    int x0 = min(max((int)gx0f, 0), WW - 1);
    int x1 = min(x0 + 1, WW - 1);
    int y0 = min(max((int)gy0f, 0), HH - 1);
    int y1 = min(y0 + 1, HH - 1);
    int xm = max(x0 - 1, 0), xp = min(x1 + 1, WW - 1), xq = max(x1 - 1, 0);
    int ym = max(y0 - 1, 0), yp = min(y1 + 1, HH - 1), yq = max(y1 - 1, 0);

    const float* r0 = pb + y0 * WW;
    const float* r1 = pb + y1 * WW;
    float v00 = r0[x0], v01 = r0[x1], v10 = r1[x0], v11 = r1[x1];
    float vm0 = r0[xm], vp0 = r0[xp], vq0 = r0[xq];
    float vm1 = r1[xm], vp1 = r1[xp], vq1 = r1[xq];
    const float* rm = pb + ym * WW;
    const float* rp = pb + yp * WW;
    const float* rq = pb + yq * WW;
    float um0 = rm[x0], um1 = rm[x1];
    float up0 = rp[x0], up1 = rp[x1];
    float uq0 = rq[x0], uq1 = rq[x1];

    float w00 = (1.0f - wx) * (1.0f - wy);
    float w01 = wx * (1.0f - wy);
    float w10 = (1.0f - wx) * wy;
    float w11 = wx * wy;

    float fs = v00 * w00 + v01 * w01 + v10 * w10 + v11 * w11;

    // gx(y, x) = 0.5*(f(y, min(x+1, W-1)) - f(y, max(x-1, 0)))
    // Note min(x0+1, W-1) == x1 by construction.
    float gx00 = 0.5f * (v01 - vm0);
    float gx01 = 0.5f * (vp0 - vq0);
    float gx10 = 0.5f * (v11 - vm1);
    float gx11 = 0.5f * (vp1 - vq1);
    float Jx = gx00 * w00 + gx01 * w01 + gx10 * w10 + gx11 * w11;

    // gy(y, x) = 0.5*(f(min(y+1, H-1), x) - f(max(y-1, 0), x))
    // Note min(y0+1, H-1) == y1 by construction.
    float gy00 = 0.5f * (v10 - um0);
    float gy01 = 0.5f * (v11 - um1);
    float gy10 = 0.5f * (up0 - uq0);
    float gy11 = 0.5f * (up1 - uq1);
    float Jy = gy00 * w00 + gy01 * w01 + gy10 * w10 + gy11 * w11;

    // ---- reductions ----
    __shared__ float sh[4][8];
    const int warp = c >> 5, lane = c & 31;

    float st = warp_sum(ft * ft);
    float ss = warp_sum(fs * fs);
    if (lane == 0) { sh[warp][0] = st; sh[warp][1] = ss; }
    __syncthreads();
    float nt = sqrtf(sh[0][0] + sh[1][0] + sh[2][0] + sh[3][0]);
    float ns = sqrtf(sh[0][1] + sh[1][1] + sh[2][1] + sh[3][1]);
    nt = fmaxf(nt, 1e-12f);
    ns = fmaxf(ns, 1e-12f);
    float r = fs / ns - ft / nt;
    __syncthreads();   // protect sh before reuse

    float sA = warp_sum(Jx * Jx);
    float sB = warp_sum(Jx * Jy);
    float sD = warp_sum(Jy * Jy);
    float s0 = warp_sum(Jx * r);
    float s1 = warp_sum(Jy * r);
    if (lane == 0) {
        sh[warp][2] = sA; sh[warp][3] = sB; sh[warp][4] = sD;
        sh[warp][5] = s0; sh[warp][6] = s1;
    }
    __syncthreads();

    if (c == 0) {
        const float EPSF = 1e-9f;
        float A  = sh[0][2] + sh[1][2] + sh[2][2] + sh[3][2] + EPSF;
        float Bo = sh[0][3] + sh[1][3] + sh[2][3] + sh[3][3];
        float D  = sh[0][4] + sh[1][4] + sh[2][4] + sh[3][4] + EPSF;
        float b0 = sh[0][5] + sh[1][5] + sh[2][5] + sh[3][5];
        float b1 = sh[0][6] + sh[1][6] + sh[2][6] + sh[3][6];
        float det = A * D - Bo * Bo;
        float inv = 1.0f / det;
        float h0 = (D * b0 - Bo * b1) * inv;     // (Hinv @ b)[0]
        float h1 = (A * b1 - Bo * b0) * inv;     // (Hinv @ b)[1]
        // diff = ub - miu = ub - xs + Hinv@b = (1 - 2*noise) + Hinv@b
        float d0 = (1.0f - 2.0f * nx) + h0;
        float d1 = (1.0f - 2.0f * ny) + h1;
        float e1 = 0.5f * (A * d0 * d0 + 2.0f * Bo * d0 * d1 + D * d1 * d1);
        g_e1[p] = e1;
        g_ld[p] = logf(det);
    }
}

__global__ __launch_bounds__(256) void gnloss_finalize(float* __restrict__ out)
{
    __shared__ double s1h[256], s2h[256];
    int t = threadIdx.x;
    double s1 = 0.0, s2 = 0.0;
    for (int i = t; i < NPTS; i += 256) {
        s1 += (double)g_e1[i];
        s2 += (double)g_ld[i];
    }
    s1h[t] = s1; s2h[t] = s2;
    __syncthreads();
    for (int o = 128; o; o >>= 1) {
        if (t < o) { s1h[t] += s1h[t + o]; s2h[t] += s2h[t + o]; }
        __syncthreads();
    }
    if (t == 0) {
        double e1 = s1h[0];
        double e2 = (double)NPTS * log(2.0 * M_PI) - 0.5 * s2h[0];
        double e  = e1 + (2.0 / 7.0) * e2;
        out[0] = (float)(0.3 * e);
        out[1] = (float)e1;
        out[2] = (float)e2;
    }
}

extern "C" void kernel_launch(void* const* d_in, const int* in_sizes, int n_in,
                              void* d_out, int out_size)
{
    const float* Fa    = (const float*)d_in[0];
    const float* Fb    = (const float*)d_in[1];
    const float* ma    = (const float*)d_in[2];
    const float* mb    = (const float*)d_in[3];
    const float* noise = (const float*)d_in[4];
    float* out = (float*)d_out;

    gnloss_point_kernel<<<NPTS, 128>>>(Fa, Fb, ma, mb, noise);
    gnloss_finalize<<<1, 256>>>(out);
}

// round 4
// speedup vs baseline: 1.1086x; 1.1086x over previous
#include <cuda_runtime.h>
#include <math.h>

// Problem constants
#define BB 4
#define CC 128
#define HH 240
#define WW 320
#define NN 1024
#define NPTS (BB * NN)

__device__ float g_e1[NPTS];
__device__ float g_ld[NPTS];
__device__ unsigned int g_count = 0;

__device__ __forceinline__ float warp_sum(float v) {
#pragma unroll
    for (int o = 16; o; o >>= 1) v += __shfl_xor_sync(0xffffffffu, v, o);
    return v;
}

__global__ __launch_bounds__(128) void gnloss_point_kernel(
    const float* __restrict__ Fa, const float* __restrict__ Fb,
    const float* __restrict__ ma, const float* __restrict__ mb,
    const float* __restrict__ noise, float* __restrict__ out)
{
    const int p = blockIdx.x;          // point index, 0..4095
    const int b = p >> 10;             // p / NN
    const int c = threadIdx.x;         // channel

    const float invL = 1.0f / 8.0f;    // 1/LEVEL
    const float2 mav = ((const float2*)ma)[p];
    const float2 mbv = ((const float2*)mb)[p];
    const float2 nzv = ((const float2*)noise)[p];
    const float xa  = mav.x * invL;
    const float ya  = mav.y * invL;
    const float ubx = mbv.x * invL;
    const float uby = mbv.y * invL;
    const float nx  = nzv.x;
    const float ny  = nzv.y;
    const float xs  = 2.0f * nx - 1.0f + ubx;
    const float ys  = 2.0f * ny - 1.0f + uby;

    // ---- f_t: bilinear sample of F_a at (xa, ya) ----
    const float* pa = Fa + (size_t)(b * CC + c) * (HH * WW);
    float fx0 = floorf(xa), fy0 = floorf(ya);
    float wxa = xa - fx0,  wya = ya - fy0;
    int ax0 = min(max((int)fx0, 0), WW - 1);
    int ax1 = min(ax0 + 1, WW - 1);
    int ay0 = min(max((int)fy0, 0), HH - 1);
    int ay1 = min(ay0 + 1, HH - 1);
    float a00 = pa[ay0 * WW + ax0], a01 = pa[ay0 * WW + ax1];
    float a10 = pa[ay1 * WW + ax0], a11 = pa[ay1 * WW + ax1];
    float ft = a00 * (1.0f - wxa) * (1.0f - wya) + a01 * wxa * (1.0f - wya)
             + a10 * (1.0f - wxa) * wya          + a11 * wxa * wya;

    // ---- F_b neighborhood for f_s, Jx, Jy ----
    const float* pb = Fb + (size_t)(b * CC + c) * (HH * WW);
    float gx0f = floorf(xs), gy0f = floorf(ys);
    float wx = xs - gx0f, wy = ys - gy0f;
    int x0 = min(max((int)gx0f, 0), WW - 1);
    int x1 = min(x0 + 1, WW - 1);
    int y0 = min(max((int)gy0f, 0), HH - 1);
    int y1 = min(y0 + 1, HH - 1);
    int xm = max(x0 - 1, 0), xp = min(x1 + 1, WW - 1), xq = max(x1 - 1, 0);
    int ym = max(y0 - 1, 0), yp = min(y1 + 1, HH - 1), yq = max(y1 - 1, 0);

    const float* r0 = pb + y0 * WW;
    const float* r1 = pb + y1 * WW;
    float v00 = r0[x0], v01 = r0[x1], v10 = r1[x0], v11 = r1[x1];
    float vm0 = r0[xm], vp0 = r0[xp], vq0 = r0[xq];
    float vm1 = r1[xm], vp1 = r1[xp], vq1 = r1[xq];
    const float* rm = pb + ym * WW;
    const float* rp = pb + yp * WW;
    const float* rq = pb + yq * WW;
    float um0 = rm[x0], um1 = rm[x1];
    float up0 = rp[x0], up1 = rp[x1];
    float uq0 = rq[x0], uq1 = rq[x1];

    float w00 = (1.0f - wx) * (1.0f - wy);
    float w01 = wx * (1.0f - wy);
    float w10 = (1.0f - wx) * wy;
    float w11 = wx * wy;

    float fs = v00 * w00 + v01 * w01 + v10 * w10 + v11 * w11;

    // gx(y, x) = 0.5*(f(y, min(x+1,W-1)) - f(y, max(x-1,0))); min(x0+1,W-1)==x1.
    float gx00 = 0.5f * (v01 - vm0);
    float gx01 = 0.5f * (vp0 - vq0);
    float gx10 = 0.5f * (v11 - vm1);
    float gx11 = 0.5f * (vp1 - vq1);
    float Jx = gx00 * w00 + gx01 * w01 + gx10 * w10 + gx11 * w11;

    // gy(y, x) = 0.5*(f(min(y+1,H-1),x) - f(max(y-1,0),x)); min(y0+1,H-1)==y1.
    float gy00 = 0.5f * (v10 - um0);
    float gy01 = 0.5f * (v11 - um1);
    float gy10 = 0.5f * (up0 - uq0);
    float gy11 = 0.5f * (up1 - uq1);
    float Jy = gy00 * w00 + gy01 * w01 + gy10 * w10 + gy11 * w11;

    // ---- reductions ----
    __shared__ float sh[4][8];
    __shared__ unsigned s_last;
    const int warp = c >> 5, lane = c & 31;

    float st = warp_sum(ft * ft);
    float ss = warp_sum(fs * fs);
    if (lane == 0) { sh[warp][0] = st; sh[warp][1] = ss; }
    __syncthreads();
    float nt = sqrtf(sh[0][0] + sh[1][0] + sh[2][0] + sh[3][0]);
    float ns = sqrtf(sh[0][1] + sh[1][1] + sh[2][1] + sh[3][1]);
    nt = fmaxf(nt, 1e-12f);
    ns = fmaxf(ns, 1e-12f);
    float r = fs / ns - ft / nt;
    __syncthreads();   // protect sh before reuse

    float sA = warp_sum(Jx * Jx);
    float sB = warp_sum(Jx * Jy);
    float sD = warp_sum(Jy * Jy);
    float s0 = warp_sum(Jx * r);
    float s1 = warp_sum(Jy * r);
    if (lane == 0) {
        sh[warp][2] = sA; sh[warp][3] = sB; sh[warp][4] = sD;
        sh[warp][5] = s0; sh[warp][6] = s1;
    }
    __syncthreads();

    if (c == 0) {
        const float EPSF = 1e-9f;
        float A  = sh[0][2] + sh[1][2] + sh[2][2] + sh[3][2] + EPSF;
        float Bo = sh[0][3] + sh[1][3] + sh[2][3] + sh[3][3];
        float D  = sh[0][4] + sh[1][4] + sh[2][4] + sh[3][4] + EPSF;
        float b0 = sh[0][5] + sh[1][5] + sh[2][5] + sh[3][5];
        float b1 = sh[0][6] + sh[1][6] + sh[2][6] + sh[3][6];
        float det = A * D - Bo * Bo;
        float inv = 1.0f / det;
        float h0 = (D * b0 - Bo * b1) * inv;     // (Hinv @ b)[0]
        float h1 = (A * b1 - Bo * b0) * inv;     // (Hinv @ b)[1]
        // diff = ub - miu = ub - xs + Hinv@b = (1 - 2*noise) + Hinv@b
        float d0 = (1.0f - 2.0f * nx) + h0;
        float d1 = (1.0f - 2.0f * ny) + h1;
        float e1 = 0.5f * (A * d0 * d0 + 2.0f * Bo * d0 * d1 + D * d1 * d1);
        g_e1[p] = e1;
        g_ld[p] = logf(det);
        __threadfence();
        unsigned prev = atomicAdd(&g_count, 1u);
        s_last = (prev == (unsigned)(NPTS - 1)) ? 1u : 0u;
    }
    __syncthreads();

    // ---- last block performs the deterministic global reduction ----
    if (s_last) {
        __threadfence();   // acquire all other blocks' g_e1/g_ld writes
        __shared__ double r1h[128], r2h[128];
        double t1 = 0.0, t2 = 0.0;
#pragma unroll 8
        for (int i = c; i < NPTS; i += 128) {
            t1 += (double)g_e1[i];
            t2 += (double)g_ld[i];
        }
        r1h[c] = t1; r2h[c] = t2;
        __syncthreads();
        for (int o = 64; o; o >>= 1) {
            if (c < o) { r1h[c] += r1h[c + o]; r2h[c] += r2h[c + o]; }
            __syncthreads();
        }
        if (c == 0) {
            double e1 = r1h[0];
            double e2 = (double)NPTS * log(2.0 * M_PI) - 0.5 * r2h[0];
            double e  = e1 + (2.0 / 7.0) * e2;
            out[0] = (float)(0.3 * e);
            out[1] = (float)e1;
            out[2] = (float)e2;
            g_count = 0;   // reset for next graph replay
        }
    }
}

extern "C" void kernel_launch(void* const* d_in, const int* in_sizes, int n_in,
                              void* d_out, int out_size)
{
    const float* Fa    = (const float*)d_in[0];
    const float* Fb    = (const float*)d_in[1];
    const float* ma    = (const float*)d_in[2];
    const float* mb    = (const float*)d_in[3];
    const float* noise = (const float*)d_in[4];
    float* out = (float*)d_out;

    gnloss_point_kernel<<<NPTS, 128>>>(Fa, Fb, ma, mb, noise, out);
}

// round 5
// speedup vs baseline: 1.1994x; 1.0819x over previous
#include <cuda_runtime.h>
#include <math.h>

// Problem constants
#define BB 4
#define CC 128
#define HH 240
#define WW 320
#define NN 1024
#define NPTS (BB * NN)

__device__ float g_e1[NPTS];
__device__ float g_ld[NPTS];
__device__ unsigned int g_count = 0;

__device__ __forceinline__ float warp_sum(float v) {
#pragma unroll
    for (int o = 16; o; o >>= 1) v += __shfl_xor_sync(0xffffffffu, v, o);
    return v;
}

__global__ __launch_bounds__(128) void gnloss_point_kernel(
    const float* __restrict__ Fa, const float* __restrict__ Fb,
    const float* __restrict__ ma, const float* __restrict__ mb,
    const float* __restrict__ noise, float* __restrict__ out)
{
    const int p = blockIdx.x;          // point index, 0..4095
    const int b = p >> 10;             // p / NN
    const int c = threadIdx.x;         // channel

    const float invL = 1.0f / 8.0f;    // 1/LEVEL
    const float2 mav = ((const float2*)ma)[p];
    const float2 mbv = ((const float2*)mb)[p];
    const float2 nzv = ((const float2*)noise)[p];
    const float xa  = mav.x * invL;
    const float ya  = mav.y * invL;
    const float ubx = mbv.x * invL;
    const float uby = mbv.y * invL;
    const float nx  = nzv.x;
    const float ny  = nzv.y;
    const float xs  = 2.0f * nx - 1.0f + ubx;
    const float ys  = 2.0f * ny - 1.0f + uby;

    // ---- f_t: bilinear sample of F_a at (xa, ya) : 4 LDG ----
    const float* pa = Fa + (size_t)(b * CC + c) * (HH * WW);
    float fx0 = floorf(xa), fy0 = floorf(ya);
    float wxa = xa - fx0,  wya = ya - fy0;
    int ax0 = min(max((int)fx0, 0), WW - 1);
    int ax1 = min(ax0 + 1, WW - 1);
    int ay0 = min(max((int)fy0, 0), HH - 1);
    int ay1 = min(ay0 + 1, HH - 1);
    float a00 = pa[ay0 * WW + ax0], a01 = pa[ay0 * WW + ax1];
    float a10 = pa[ay1 * WW + ax0], a11 = pa[ay1 * WW + ax1];
    float ft = a00 * (1.0f - wxa) * (1.0f - wya) + a01 * wxa * (1.0f - wya)
             + a10 * (1.0f - wxa) * wya          + a11 * wxa * wya;

    // ---- F_b neighborhood for f_s, Jx, Jy : 12 LDG ----
    const float* pb = Fb + (size_t)(b * CC + c) * (HH * WW);
    float gx0f = floorf(xs), gy0f = floorf(ys);
    float wx = xs - gx0f, wy = ys - gy0f;
    int x0 = min(max((int)gx0f, 0), WW - 1);
    int x1 = min(x0 + 1, WW - 1);
    int y0 = min(max((int)gy0f, 0), HH - 1);
    int y1 = min(y0 + 1, HH - 1);
    int xm = max(x0 - 1, 0), xp = min(x1 + 1, WW - 1);
    int ym = max(y0 - 1, 0), yp = min(y1 + 1, HH - 1);

    const float* r0 = pb + y0 * WW;
    const float* r1 = pb + y1 * WW;
    const float* rm = pb + ym * WW;
    const float* rp = pb + yp * WW;
    // row y0: xm, x0, x1, xp  (4)
    float vm0 = r0[xm], v00 = r0[x0], v01 = r0[x1], vp0 = r0[xp];
    // row y1: xm, x0, x1, xp  (4)
    float vm1 = r1[xm], v10 = r1[x0], v11 = r1[x1], vp1 = r1[xp];
    // row ym: x0, x1          (2)
    float um0 = rm[x0], um1 = rm[x1];
    // row yp: x0, x1          (2)
    float up0 = rp[x0], up1 = rp[x1];

    // Deduped values:
    // xq = max(x1-1, 0): if x1 > x0 then xq == x0; else (x1==x0, i.e. both
    // clamped to the same column) xq == max(x0-1,0) == xm. When x0==x1==0,
    // v00 == vm0 so the select is still exact.
    float vq0 = (x1 > x0) ? v00 : vm0;
    float vq1 = (x1 > x0) ? v10 : vm1;
    // yq = max(y1-1, 0): same logic on rows. uq row == y0 normally, == ym on clamp.
    float uq0 = (y1 > y0) ? v00 : um0;
    float uq1 = (y1 > y0) ? v01 : um1;

    float w00 = (1.0f - wx) * (1.0f - wy);
    float w01 = wx * (1.0f - wy);
    float w10 = (1.0f - wx) * wy;
    float w11 = wx * wy;

    float fs = v00 * w00 + v01 * w01 + v10 * w10 + v11 * w11;

    // gx(y, x) = 0.5*(f(y, min(x+1,W-1)) - f(y, max(x-1,0))); min(x0+1,W-1)==x1.
    float gx00 = 0.5f * (v01 - vm0);
    float gx01 = 0.5f * (vp0 - vq0);
    float gx10 = 0.5f * (v11 - vm1);
    float gx11 = 0.5f * (vp1 - vq1);
    float Jx = gx00 * w00 + gx01 * w01 + gx10 * w10 + gx11 * w11;

    // gy(y, x) = 0.5*(f(min(y+1,H-1),x) - f(max(y-1,0),x)); min(y0+1,H-1)==y1.
    float gy00 = 0.5f * (v10 - um0);
    float gy01 = 0.5f * (v11 - um1);
    float gy10 = 0.5f * (up0 - uq0);
    float gy11 = 0.5f * (up1 - uq1);
    float Jy = gy00 * w00 + gy01 * w01 + gy10 * w10 + gy11 * w11;

    // ---- reductions ----
    __shared__ float sh[4][8];
    __shared__ unsigned s_last;
    const int warp = c >> 5, lane = c & 31;

    float st = warp_sum(ft * ft);
    float ss = warp_sum(fs * fs);
    if (lane == 0) { sh[warp][0] = st; sh[warp][1] = ss; }
    __syncthreads();
    float nt = sqrtf(sh[0][0] + sh[1][0] + sh[2][0] + sh[3][0]);
    float ns = sqrtf(sh[0][1] + sh[1][1] + sh[2][1] + sh[3][1]);
    nt = fmaxf(nt, 1e-12f);
    ns = fmaxf(ns, 1e-12f);
    float r = fs / ns - ft / nt;
    __syncthreads();   // protect sh before reuse

    float sA = warp_sum(Jx * Jx);
    float sB = warp_sum(Jx * Jy);
    float sD = warp_sum(Jy * Jy);
    float s0 = warp_sum(Jx * r);
    float s1 = warp_sum(Jy * r);
    if (lane == 0) {
        sh[warp][2] = sA; sh[warp][3] = sB; sh[warp][4] = sD;
        sh[warp][5] = s0; sh[warp][6] = s1;
    }
    __syncthreads();

    if (c == 0) {
        const float EPSF = 1e-9f;
        float A  = sh[0][2] + sh[1][2] + sh[2][2] + sh[3][2] + EPSF;
        float Bo = sh[0][3] + sh[1][3] + sh[2][3] + sh[3][3];
        float D  = sh[0][4] + sh[1][4] + sh[2][4] + sh[3][4] + EPSF;
        float b0 = sh[0][5] + sh[1][5] + sh[2][5] + sh[3][5];
        float b1 = sh[0][6] + sh[1][6] + sh[2][6] + sh[3][6];
        float det = A * D - Bo * Bo;
        float inv = 1.0f / det;
        float h0 = (D * b0 - Bo * b1) * inv;     // (Hinv @ b)[0]
        float h1 = (A * b1 - Bo * b0) * inv;     // (Hinv @ b)[1]
        // diff = ub - miu = ub - xs + Hinv@b = (1 - 2*noise) + Hinv@b
        float d0 = (1.0f - 2.0f * nx) + h0;
        float d1 = (1.0f - 2.0f * ny) + h1;
        float e1 = 0.5f * (A * d0 * d0 + 2.0f * Bo * d0 * d1 + D * d1 * d1);
        g_e1[p] = e1;
        g_ld[p] = logf(det);
        __threadfence();
        unsigned prev = atomicAdd(&g_count, 1u);
        s_last = (prev == (unsigned)(NPTS - 1)) ? 1u : 0u;
    }
    __syncthreads();

    // ---- last block performs the deterministic global reduction ----
    if (s_last) {
        __threadfence();   // acquire all other blocks' g_e1/g_ld writes
        __shared__ double r1h[128], r2h[128];
        double t1 = 0.0, t2 = 0.0;
#pragma unroll 8
        for (int i = c; i < NPTS; i += 128) {
            t1 += (double)g_e1[i];
            t2 += (double)g_ld[i];
        }
        r1h[c] = t1; r2h[c] = t2;
        __syncthreads();
        for (int o = 64; o; o >>= 1) {
            if (c < o) { r1h[c] += r1h[c + o]; r2h[c] += r2h[c + o]; }
            __syncthreads();
        }
        if (c == 0) {
            double e1 = r1h[0];
            double e2 = (double)NPTS * log(2.0 * M_PI) - 0.5 * r2h[0];
            double e  = e1 + (2.0 / 7.0) * e2;
            out[0] = (float)(0.3 * e);
            out[1] = (float)e1;
            out[2] = (float)e2;
            g_count = 0;   // reset for next graph replay
        }
    }
}

extern "C" void kernel_launch(void* const* d_in, const int* in_sizes, int n_in,
                              void* d_out, int out_size)
{
    const float* Fa    = (const float*)d_in[0];
    const float* Fb    = (const float*)d_in[1];
    const float* ma    = (const float*)d_in[2];
    const float* mb    = (const float*)d_in[3];
    const float* noise = (const float*)d_in[4];
    float* out = (float*)d_out;

    gnloss_point_kernel<<<NPTS, 128>>>(Fa, Fb, ma, mb, noise, out);
}